// round 11
// baseline (speedup 1.0000x reference)
#include <cuda_runtime.h>

#define X 256
#define Y 256
#define Z 192
#define YX (X*Y)
#define NB 2
#define TX 64           // output tile width
#define TY 32           // output tile height
#define CW 34           // float2 cells per row = (TX+4)/2
#define CH 36           // rows = TY+4
#define TCX 17          // thread columns (each owns 2 adjacent cells)
#define TCY 18          // thread rows (each owns 2 adjacent rows)
#define NTH (TCX*TCY)   // 306 threads
#define ZCHUNKS 8
#define ZCK (Z/ZCHUNKS) /* 24 */

__device__ __forceinline__ float min3(float a, float b, float c) { return fminf(a, fminf(b, c)); }
__device__ __forceinline__ float max3(float a, float b, float c) { return fmaxf(a, fmaxf(b, c)); }
__device__ __forceinline__ float2 fmin3_2(float2 a, float2 b, float2 c) {
    return make_float2(min3(a.x,b.x,c.x), min3(a.y,b.y,c.y));
}
__device__ __forceinline__ float2 fmax3_2(float2 a, float2 b, float2 c) {
    return make_float2(max3(a.x,b.x,c.x), max3(a.y,b.y,c.y));
}

// out = relu(img - dilate3x3x3(erode3x3x3(img))), stride 1, pad 1.
// erode = min-pool (pad +inf), dilate = max-pool (pad -inf via domain mask).
// Same 4-round LDS.64 ping-pong as the 84.7us champion, but each thread owns
// a 2x2 patch of float2 cells (8 voxels): inner x-window is in-register, so
// smem ops fall to 4 per output voxel and barrier participation halves again.
// 306-thread blocks, 3 per SM = 3 independent barrier domains.
__global__ __launch_bounds__(NTH, 3)
void soft_skel_kernel(const float* __restrict__ img, float* __restrict__ out) {
    __shared__ float2 sA[CH * CW];
    __shared__ float2 sB[CH * CW];

    const int tid = threadIdx.x;
    const int tc  = tid % TCX;           // owns cells 2tc, 2tc+1
    const int tr  = tid / TCX;           // owns rows 2tr, 2tr+1
    const int bx0 = blockIdx.x * TX;
    const int by0 = blockIdx.y * TY;
    const int bz  = blockIdx.z;
    const int b   = bz / ZCHUNKS;
    const int z0  = (bz % ZCHUNKS) * ZCK;
    const int z1  = z0 + ZCK;

    const int gx0 = bx0 + 4*tc - 2;      // x of cell c0 (even)
    const int gy0 = by0 + 2*tr - 2;      // y of row r0

    // each float2 cell is uniformly inside or outside in x (gx even, X even)
    const bool inx0 = (gx0 >= 0)     && (gx0 < X);
    const bool inx1 = (gx0 + 2 >= 0) && (gx0 + 2 < X);
    const bool iny0 = (gy0 >= 0)     && (gy0 < Y);
    const bool iny1 = (gy0 + 1 >= 0) && (gy0 + 1 < Y);

    // output predicates: rows 2..33 (tr 1..16), cells 1..32
    const bool outRow = (tr >= 1) && (tr <= TCY - 2);
    const bool outC0  = (tc >= 1);                // cell 2tc   >= 2... >=1 ok
    const bool outC1  = (tc <= TCX - 2);          // cell 2tc+1 <= 31

    // smem offsets (float2 units); clamps leave garbage only in shell
    const int yu  = (tr == 0)       ? 0      : 2*tr - 1;
    const int yd  = (tr == TCY - 1) ? CH - 1 : 2*tr + 2;
    const int xl  = (tc == 0)       ? 0      : 2*tc - 1;
    const int xr  = (tc == TCX - 1) ? CW - 1 : 2*tc + 2;
    const int o0  = (2*tr)     * CW + 2*tc;   // row r0, cell c0 (+1 = c1)
    const int o1  = (2*tr + 1) * CW + 2*tc;   // row r1
    const int oU  = yu * CW + 2*tc;           // (+1 = c1)
    const int oD  = yd * CW + 2*tc;
    const int oL0 = (2*tr)     * CW + xl;
    const int oL1 = (2*tr + 1) * CW + xl;
    const int oR0 = (2*tr)     * CW + xr;
    const int oR1 = (2*tr + 1) * CW + xr;

    const float  PINF = __int_as_float(0x7f800000);
    const float  NINF = __int_as_float(0xff800000);
    const float2 PI2  = make_float2(PINF, PINF);
    const float2 NI2  = make_float2(NINF, NINF);

    const long base = (long)b * Z * YX + (long)gy0 * X + gx0;
    const float* pIn = img + base;       // + z*YX
    float*       pO  = out + base + (long)z0 * YX;

    // rings: p = img planes (zi-2, zi-1, zi), q = erode planes (zi-3, zi-2)
    float2 p0[2][2], p1[2][2], p2[2][2];
    float2 q0[2][2], q1[2][2];
    #pragma unroll
    for (int r = 0; r < 2; ++r)
        #pragma unroll
        for (int c = 0; c < 2; ++c) {
            p0[r][c] = PI2; p1[r][c] = PI2;
            q0[r][c] = NI2; q1[r][c] = NI2;
        }

    // masked plane load into dst[2][2]
    #define LOADP(dst, zz) do {                                           \
        const int _z = (zz);                                              \
        const bool _zk = (unsigned)_z < (unsigned)Z;                      \
        const long _o = (long)_z * YX;                                    \
        dst[0][0] = (_zk && iny0 && inx0) ? *(const float2*)(pIn + _o)          : PI2; \
        dst[0][1] = (_zk && iny0 && inx1) ? *(const float2*)(pIn + _o + 2)      : PI2; \
        dst[1][0] = (_zk && iny1 && inx0) ? *(const float2*)(pIn + _o + X)      : PI2; \
        dst[1][1] = (_zk && iny1 && inx1) ? *(const float2*)(pIn + _o + X + 2)  : PI2; \
    } while (0)

    LOADP(p2, z0 - 2);

    for (int zi = z0 - 2; zi <= z1 + 1; ++zi) {
        // ---- prefetch plane zi+1 (4 barrier-phases ahead of use)
        float2 pn[2][2];
        LOADP(pn, zi + 1);

        // ---- erode-z (registers) at plane zc = zi-1
        float2 zm[2][2];
        #pragma unroll
        for (int r = 0; r < 2; ++r)
            #pragma unroll
            for (int c = 0; c < 2; ++c)
                zm[r][c] = fmin3_2(p0[r][c], p1[r][c], p2[r][c]);

        // ---- erode-y via smem (buffer A): 1 up + 1 down per column
        sA[o0]     = zm[0][0];
        sA[o0 + 1] = zm[0][1];
        sA[o1]     = zm[1][0];
        sA[o1 + 1] = zm[1][1];
        __syncthreads();
        float2 yb[2][2];
        {
            float2 U0 = sA[oU], U1 = sA[oU + 1];
            float2 D0 = sA[oD], D1 = sA[oD + 1];
            yb[0][0] = fmin3_2(U0, zm[0][0], zm[1][0]);
            yb[0][1] = fmin3_2(U1, zm[0][1], zm[1][1]);
            yb[1][0] = fmin3_2(zm[0][0], zm[1][0], D0);
            yb[1][1] = fmin3_2(zm[0][1], zm[1][1], D1);
        }
        sB[o0]     = yb[0][0];
        sB[o0 + 1] = yb[0][1];
        sB[o1]     = yb[1][0];
        sB[o1 + 1] = yb[1][1];
        __syncthreads();

        // ---- erode-x: inner lanes in-register, 1 L + 1 R cell per row
        float2 en[2][2];
        {
            float2 L0 = sB[oL0], R0 = sB[oR0];
            float2 L1 = sB[oL1], R1 = sB[oR1];
            const int  zc  = zi - 1;
            const bool zin = (unsigned)zc < (unsigned)Z;
            const bool m00 = zin && iny0 && inx0, m01 = zin && iny0 && inx1;
            const bool m10 = zin && iny1 && inx0, m11 = zin && iny1 && inx1;
            en[0][0].x = m00 ? min3(L0.y,      yb[0][0].x, yb[0][0].y) : NINF;
            en[0][0].y = m00 ? min3(yb[0][0].x, yb[0][0].y, yb[0][1].x) : NINF;
            en[0][1].x = m01 ? min3(yb[0][0].y, yb[0][1].x, yb[0][1].y) : NINF;
            en[0][1].y = m01 ? min3(yb[0][1].x, yb[0][1].y, R0.x)      : NINF;
            en[1][0].x = m10 ? min3(L1.y,      yb[1][0].x, yb[1][0].y) : NINF;
            en[1][0].y = m10 ? min3(yb[1][0].x, yb[1][0].y, yb[1][1].x) : NINF;
            en[1][1].x = m11 ? min3(yb[1][0].y, yb[1][1].x, yb[1][1].y) : NINF;
            en[1][1].y = m11 ? min3(yb[1][1].x, yb[1][1].y, R1.x)      : NINF;
        }

        // ---- dilate-z (registers) at plane zo = zi-2
        float2 dd[2][2];
        #pragma unroll
        for (int r = 0; r < 2; ++r)
            #pragma unroll
            for (int c = 0; c < 2; ++c) {
                dd[r][c] = fmax3_2(q0[r][c], q1[r][c], en[r][c]);
                q0[r][c] = q1[r][c]; q1[r][c] = en[r][c];
            }

        // ---- dilate-y via smem (buffer A reusable after sync above)
        sA[o0]     = dd[0][0];
        sA[o0 + 1] = dd[0][1];
        sA[o1]     = dd[1][0];
        sA[o1 + 1] = dd[1][1];
        __syncthreads();
        float2 m[2][2];
        {
            float2 U0 = sA[oU], U1 = sA[oU + 1];
            float2 D0 = sA[oD], D1 = sA[oD + 1];
            m[0][0] = fmax3_2(U0, dd[0][0], dd[1][0]);
            m[0][1] = fmax3_2(U1, dd[0][1], dd[1][1]);
            m[1][0] = fmax3_2(dd[0][0], dd[1][0], D0);
            m[1][1] = fmax3_2(dd[0][1], dd[1][1], D1);
        }
        sB[o0]     = m[0][0];
        sB[o0 + 1] = m[0][1];
        sB[o1]     = m[1][0];
        sB[o1 + 1] = m[1][1];
        __syncthreads();

        // ---- dilate-x + output: opened at plane zo = zi-2
        if (zi >= z0 + 2) {
            if (outRow) {
                float2 L0 = sB[oL0], R0 = sB[oR0];
                float2 L1 = sB[oL1], R1 = sB[oR1];
                if (outC0) {
                    float2 r0, r1;
                    r0.x = fmaxf(p0[0][0].x - max3(L0.y, m[0][0].x, m[0][0].y), 0.0f);
                    r0.y = fmaxf(p0[0][0].y - max3(m[0][0].x, m[0][0].y, m[0][1].x), 0.0f);
                    r1.x = fmaxf(p0[1][0].x - max3(L1.y, m[1][0].x, m[1][0].y), 0.0f);
                    r1.y = fmaxf(p0[1][0].y - max3(m[1][0].x, m[1][0].y, m[1][1].x), 0.0f);
                    *(float2*)pO       = r0;    // p0 = img at plane zo
                    *(float2*)(pO + X) = r1;
                }
                if (outC1) {
                    float2 r0, r1;
                    r0.x = fmaxf(p0[0][1].x - max3(m[0][0].y, m[0][1].x, m[0][1].y), 0.0f);
                    r0.y = fmaxf(p0[0][1].y - max3(m[0][1].x, m[0][1].y, R0.x), 0.0f);
                    r1.x = fmaxf(p0[1][1].x - max3(m[1][0].y, m[1][1].x, m[1][1].y), 0.0f);
                    r1.y = fmaxf(p0[1][1].y - max3(m[1][1].x, m[1][1].y, R1.x), 0.0f);
                    *(float2*)(pO + 2)     = r0;
                    *(float2*)(pO + X + 2) = r1;
                }
            }
            pO += YX;
        }

        // ---- shift img rings
        #pragma unroll
        for (int r = 0; r < 2; ++r)
            #pragma unroll
            for (int c = 0; c < 2; ++c) {
                p0[r][c] = p1[r][c]; p1[r][c] = p2[r][c]; p2[r][c] = pn[r][c];
            }
    }
    #undef LOADP
}

extern "C" void kernel_launch(void* const* d_in, const int* in_sizes, int n_in,
                              void* d_out, int out_size) {
    (void)in_sizes; (void)n_in; (void)out_size;
    const float* img = (const float*)d_in[0];
    float* out = (float*)d_out;
    dim3 grid(X / TX, Y / TY, NB * ZCHUNKS);
    soft_skel_kernel<<<grid, NTH>>>(img, out);
}